// round 16
// baseline (speedup 1.0000x reference)
#include <cuda_runtime.h>
#include <cuda_fp16.h>
#include <cstdint>

#define BB 4
#define TT 2048
#define CC 1024
#define HH 16
#define DD 64
#define MM (BB*TT)   // 8192

// logits pre-scale: 1/sqrt(D) * log2(e), folded into q at projection time
#define QSCALE 0.18033688011112042f

// ---------------------------------------------------------------------------
// Scratch (device globals, 16B aligned)
// ---------------------------------------------------------------------------
__device__ __align__(16) __half g_xh[(size_t)MM*CC];
__device__ __align__(16) __half g_wh[(size_t)4*CC*CC];   // q,k,v,p
__device__ __align__(16) __half g_qh[(size_t)MM*CC];     // [B,H,T,D] (pre-scaled)
__device__ __align__(16) __half g_kh[(size_t)MM*CC];
__device__ __align__(16) __half g_vh[(size_t)MM*CC];
__device__ __align__(16) __half g_yh[(size_t)MM*CC];     // [B,T,C]

// ---------------------------------------------------------------------------
// PTX helpers
// ---------------------------------------------------------------------------
__device__ __forceinline__ uint32_t smem_u32(const void* p) {
    uint32_t a;
    asm("{ .reg .u64 t; cvta.to.shared.u64 t, %1; cvt.u32.u64 %0, t; }"
        : "=r"(a) : "l"(p));
    return a;
}
__device__ __forceinline__ void cp16(uint32_t dst, const void* src) {
    asm volatile("cp.async.cg.shared.global [%0], [%1], 16;" :: "r"(dst), "l"(src));
}
__device__ __forceinline__ void cp_commit() {
    asm volatile("cp.async.commit_group;" ::: "memory");
}
template<int N> __device__ __forceinline__ void cp_wait() {
    asm volatile("cp.async.wait_group %0;" :: "n"(N) : "memory");
}
__device__ __forceinline__ void ldsm4(uint32_t* r, uint32_t a) {
    asm volatile("ldmatrix.sync.aligned.m8n8.x4.shared.b16 {%0,%1,%2,%3}, [%4];"
        : "=r"(r[0]), "=r"(r[1]), "=r"(r[2]), "=r"(r[3]) : "r"(a));
}
__device__ __forceinline__ void ldsm4t(uint32_t* r, uint32_t a) {
    asm volatile("ldmatrix.sync.aligned.m8n8.x4.trans.shared.b16 {%0,%1,%2,%3}, [%4];"
        : "=r"(r[0]), "=r"(r[1]), "=r"(r[2]), "=r"(r[3]) : "r"(a));
}
__device__ __forceinline__ void mma_f16(float* d, const uint32_t* a, uint32_t b0, uint32_t b1) {
    asm volatile(
        "mma.sync.aligned.m16n8k16.row.col.f32.f16.f16.f32 "
        "{%0,%1,%2,%3}, {%4,%5,%6,%7}, {%8,%9}, {%0,%1,%2,%3};"
        : "+f"(d[0]), "+f"(d[1]), "+f"(d[2]), "+f"(d[3])
        : "r"(a[0]), "r"(a[1]), "r"(a[2]), "r"(a[3]), "r"(b0), "r"(b1));
}
__device__ __forceinline__ uint32_t pack2(float a, float b) {
    __half2 h = __float22half2_rn(make_float2(a, b));   // single F2FP.PACK
    return *(uint32_t*)&h;
}

// ---------------------------------------------------------------------------
// Fused conversion: x -> fp16, W{q,k,v,p} -> fp16. 2 elems/thread.
// ---------------------------------------------------------------------------
#define XPAIRS ((size_t)MM*CC/2)     // 4194304
#define WPAIRS ((size_t)CC*CC/2)     // 524288

__global__ void cvt_inputs(const float* __restrict__ x,
                           const float* __restrict__ Wq, const float* __restrict__ Wk,
                           const float* __restrict__ Wv, const float* __restrict__ Wp) {
    size_t i = (size_t)blockIdx.x * blockDim.x + threadIdx.x;
    if (i < XPAIRS) {
        float2 v = ((const float2*)x)[i];
        ((__half2*)g_xh)[i] = __float22half2_rn(make_float2(v.x, v.y));
    } else {
        size_t j = i - XPAIRS;
        int which = (int)(j >> 19);
        size_t wi = j & (WPAIRS - 1);
        const float* src = (which == 0) ? Wq : (which == 1) ? Wk : (which == 2) ? Wv : Wp;
        float2 v = ((const float2*)src)[wi];
        ((__half2*)g_wh)[(size_t)which * WPAIRS + wi] =
            __float22half2_rn(make_float2(v.x, v.y));
    }
}

// ---------------------------------------------------------------------------
// GEMM: C[128x128] = Ah * Wh^T, fp16 1-term.
// 128 threads = 4 warps (2m x 2n), warp tile 64x64, 2 CTAs/SM.
// smem: 2 stages x (Ah 128x32, Bh 128x32) fp16, row stride 40.
// ---------------------------------------------------------------------------
#define GSTR 40
#define GA_ELEMS (128*GSTR)          // 5120 elems per tile (A and B same shape)
#define GSTAGE_B (2*GA_ELEMS*2)      // 20480 bytes per stage
#define GSMEM (2*GSTAGE_B)           // 40960

__device__ __forceinline__ void gemm_issue(
    uint32_t sb, int stage,
    const __half* __restrict__ Ah, const __half* __restrict__ Bh,
    int m0, int n0, int k0)
{
    const int t = threadIdx.x;
    const uint32_t stb = sb + stage * GSTAGE_B;
    #pragma unroll
    for (int i = 0; i < 4; i++) {
        int idx = i * 128 + t;                 // 0..511
        int row = idx >> 2, c16 = idx & 3;
        cp16(stb + (uint32_t)(row * GSTR + c16 * 8) * 2,
             Ah + (size_t)(m0 + row) * CC + k0 + c16 * 8);
    }
    #pragma unroll
    for (int i = 0; i < 4; i++) {
        int idx = i * 128 + t;
        int row = idx >> 2, c16 = idx & 3;
        cp16(stb + (uint32_t)(GA_ELEMS + row * GSTR + c16 * 8) * 2,
             Bh + (size_t)(n0 + row) * CC + k0 + c16 * 8);
    }
}

__device__ __forceinline__ void gemm_body(
    const __half* __restrict__ Ah, const __half* __restrict__ Bh,
    int m0, int n0, uint32_t sb, float acc[4][8][4])
{
    const int l   = threadIdx.x & 31;
    const int wid = threadIdx.x >> 5;
    const int wm  = wid >> 1;            // 0..1
    const int wn  = wid & 1;             // 0..1

    #pragma unroll
    for (int mf = 0; mf < 4; mf++)
        #pragma unroll
        for (int nf = 0; nf < 8; nf++)
            #pragma unroll
            for (int q = 0; q < 4; q++) acc[mf][nf][q] = 0.f;

    gemm_issue(sb, 0, Ah, Bh, m0, n0, 0);
    cp_commit();

    const uint32_t lrow = (l & 15);
    const uint32_t lkad = ((l >> 4) << 3);

    #pragma unroll 1
    for (int c = 0; c < 32; c++) {
        cp_wait<0>();            // chunk c landed
        __syncthreads();         // all 4 warps done with chunk c-1 -> stage free
        if (c + 1 < 32)
            gemm_issue(sb, (c + 1) & 1, Ah, Bh, m0, n0, (c + 1) * 32);
        cp_commit();             // uniform group count

        const uint32_t stb = sb + (c & 1) * GSTAGE_B;
        const uint32_t tAh = stb;
        const uint32_t tBh = stb + GA_ELEMS * 2;

        #pragma unroll
        for (int ks = 0; ks < 32; ks += 16) {
            uint32_t ah[4][4];
            #pragma unroll
            for (int mf = 0; mf < 4; mf++) {
                uint32_t off = (uint32_t)((wm * 64 + mf * 16 + lrow) * GSTR + ks + lkad) * 2;
                ldsm4(ah[mf], tAh + off);
            }
            uint32_t bh[8][2];
            #pragma unroll
            for (int p = 0; p < 4; p++) {
                uint32_t off = (uint32_t)((wn * 64 + p * 16 + lrow) * GSTR + ks + lkad) * 2;
                uint32_t r[4];
                ldsm4(r, tBh + off);
                bh[2*p][0]   = r[0]; bh[2*p][1]   = r[2];
                bh[2*p+1][0] = r[1]; bh[2*p+1][1] = r[3];
            }
            #pragma unroll
            for (int mf = 0; mf < 4; mf++)
                #pragma unroll
                for (int nf = 0; nf < 8; nf++)
                    mma_f16(acc[mf][nf], ah[mf], bh[nf][0], bh[nf][1]);
        }
    }
}

// Fused QKV projection (1-term): grid (8, 64, 3). [B,H,T,D] fp16 out.
// q gets QSCALE folded in.
__global__ __launch_bounds__(128, 2)
void gemm_qkv() {
    extern __shared__ __align__(16) char gsm[];
    const uint32_t sb = smem_u32(gsm);
    const int which = blockIdx.z;            // 0=Q, 1=K, 2=V
    const int m0 = blockIdx.y * 128;
    const int n0 = blockIdx.x * 128;
    const __half* Wh = g_wh + (size_t)which * CC * CC;

    float acc[4][8][4];
    gemm_body(g_xh, Wh, m0, n0, sb, acc);

    __half* dst = (which == 0) ? g_qh : (which == 1) ? g_kh : g_vh;
    const float scl = (which == 0) ? QSCALE : 1.0f;
    const int l   = threadIdx.x & 31;
    const int wid = threadIdx.x >> 5;
    const int wm  = wid >> 1, wn = wid & 1;

    #pragma unroll
    for (int mf = 0; mf < 4; mf++) {
        #pragma unroll
        for (int nf = 0; nf < 8; nf++) {
            int col = n0 + wn * 64 + nf * 8 + (l & 3) * 2;
            int hh = col >> 6, d = col & 63;
            #pragma unroll
            for (int hf = 0; hf < 2; hf++) {
                int m = m0 + wm * 64 + mf * 16 + (l >> 2) + hf * 8;
                int b = m >> 11, t = m & (TT - 1);
                size_t idx = (((size_t)(b * HH + hh) * TT + t) << 6) + d;
                *(uint32_t*)&dst[idx] = pack2(acc[mf][nf][hf*2 + 0] * scl,
                                              acc[mf][nf][hf*2 + 1] * scl);
            }
        }
    }
}

// Output projection (1-term): grid (8, 64); fp32 out
__global__ __launch_bounds__(128, 2)
void gemm_proj(float* __restrict__ out) {
    extern __shared__ __align__(16) char gsm[];
    const uint32_t sb = smem_u32(gsm);
    const int m0 = blockIdx.y * 128;
    const int n0 = blockIdx.x * 128;
    const __half* Wh = g_wh + (size_t)3 * CC * CC;

    float acc[4][8][4];
    gemm_body(g_yh, Wh, m0, n0, sb, acc);

    const int l   = threadIdx.x & 31;
    const int wid = threadIdx.x >> 5;
    const int wm  = wid >> 1, wn = wid & 1;

    #pragma unroll
    for (int mf = 0; mf < 4; mf++)
        #pragma unroll
        for (int nf = 0; nf < 8; nf++) {
            int col = n0 + wn * 64 + nf * 8 + (l & 3) * 2;
            #pragma unroll
            for (int hf = 0; hf < 2; hf++) {
                int m = m0 + wm * 64 + mf * 16 + (l >> 2) + hf * 8;
                *(float2*)&out[(size_t)m * CC + col] =
                    make_float2(acc[mf][nf][hf*2 + 0], acc[mf][nf][hf*2 + 1]);
            }
        }
}

// ---------------------------------------------------------------------------
// Flash attention (unchanged from round 12). grid (32, 64), 128 thr.
// BR=64 (16/warp), BC=64. exp2f softmax, QK 1-term, PV 1-term.
// KV 2-stage cp.async ring, 4 CTAs/SM.
// ---------------------------------------------------------------------------
#define FSTR 72
#define FKV_T (64*FSTR)              // 4608 elems per KV tile
#define FKV_STAGE_B (2*FKV_T*2)      // 18432 bytes per stage (Kh, Vh)
#define FQ_T (64*FSTR)               // 4608 elems Q tile
#define FQ_OFF (2*FKV_STAGE_B)       // 36864
#define FSMEM (FQ_OFF + FQ_T*2)      // 46080

__device__ __forceinline__ void kv_issue(uint32_t sb, int stage, size_t hb, int jt) {
    const int t = threadIdx.x;
    const uint32_t stb = sb + stage * FKV_STAGE_B;
    #pragma unroll
    for (int i = 0; i < 8; i++) {
        const int tile = i >> 2;                 // 0=K, 1=V
        int idx = ((i & 3) << 7) | t;            // 0..511
        int row = idx >> 3;
        int c16 = idx & 7;
        size_t go = hb + (size_t)(jt * 64 + row) * DD + c16 * 8;
        const __half* src = (tile == 0) ? (g_kh + go) : (g_vh + go);
        cp16(stb + (uint32_t)(tile * FKV_T + row * FSTR + c16 * 8) * 2, src);
    }
}

__global__ __launch_bounds__(128, 4)
void flash_mma() {
    extern __shared__ __align__(16) char fsm[];
    const uint32_t sb = smem_u32(fsm);

    const int tid = threadIdx.x;
    const int l   = tid & 31;
    const int w   = tid >> 5;            // 0..3
    const int qt  = (int)(gridDim.x - 1 - blockIdx.x);
    const int bh  = blockIdx.y;
    const int b   = bh >> 4;
    const int hh  = bh & 15;
    const size_t hb = (size_t)bh * TT * DD;
    const int ntile = qt + 1;

    // Q load + kv0 in one group
    #pragma unroll
    for (int i = 0; i < 4; i++) {
        int idx = (i << 7) | tid;                // 0..511
        int row = idx >> 3;
        int c16 = idx & 7;
        const __half* src = g_qh + hb + (size_t)(qt * 64 + row) * DD + c16 * 8;
        cp16(sb + FQ_OFF + (uint32_t)(row * FSTR + c16 * 8) * 2, src);
    }
    kv_issue(sb, 0, hb, 0);
    cp_commit();

    float s[8][4], o[8][4];
    float m0_ = -1e30f, m1_ = -1e30f, l0_ = 0.f, l1_ = 0.f;
    #pragma unroll
    for (int nf = 0; nf < 8; nf++)
        #pragma unroll
        for (int q = 0; q < 4; q++) o[nf][q] = 0.f;

    const uint32_t sQh = sb + FQ_OFF;
    const uint32_t lrow = (l & 15);
    const uint32_t lkad = ((l >> 4) << 3);

    #pragma unroll 1
    for (int jt = 0; jt < ntile; jt++) {
        cp_wait<0>();
        __syncthreads();
        if (jt + 1 < ntile)
            kv_issue(sb, (jt + 1) & 1, hb, jt + 1);
        cp_commit();

        const uint32_t kvb = sb + (jt & 1) * FKV_STAGE_B;
        const uint32_t sKh = kvb;
        const uint32_t sVh = kvb + FKV_T * 2;

        // ---- S = Q K^T ----
        #pragma unroll
        for (int nf = 0; nf < 8; nf++)
            #pragma unroll
            for (int q = 0; q < 4; q++) s[nf][q] = 0.f;

        #pragma unroll
        for (int kd = 0; kd < 4; kd++) {
            uint32_t qh[4];
            uint32_t offq = (uint32_t)((w * 16 + lrow) * FSTR + kd * 16 + lkad) * 2;
            ldsm4(qh, sQh + offq);
            uint32_t rk[4][4];
            #pragma unroll
            for (int p = 0; p < 4; p++) {
                uint32_t offk = (uint32_t)((p * 16 + lrow) * FSTR + kd * 16 + lkad) * 2;
                ldsm4(rk[p], sKh + offk);
            }
            #pragma unroll
            for (int p = 0; p < 4; p++) {
                mma_f16(s[2*p],   qh, rk[p][0], rk[p][2]);
                mma_f16(s[2*p+1], qh, rk[p][1], rk[p][3]);
            }
        }

        // ---- causal mask ----
        const int row_lo = qt * 64 + w * 16 + (l >> 2);
        const int row_hi = row_lo + 8;
        const int col0 = jt * 64 + (l & 3) * 2;
        if (jt == qt) {
            #pragma unroll
            for (int nf = 0; nf < 8; nf++) {
                int c = col0 + nf * 8;
                if (c     > row_lo) s[nf][0] = -1e30f;
                if (c + 1 > row_lo) s[nf][1] = -1e30f;
                if (c     > row_hi) s[nf][2] = -1e30f;
                if (c + 1 > row_hi) s[nf][3] = -1e30f;
            }
        }

        // ---- online softmax (base 2) ----
        float mt0 = -1e30f, mt1 = -1e30f;
        #pragma unroll
        for (int nf = 0; nf < 8; nf++) {
            mt0 = fmaxf(mt0, fmaxf(s[nf][0], s[nf][1]));
            mt1 = fmaxf(mt1, fmaxf(s[nf][2], s[nf][3]));
        }
        mt0 = fmaxf(mt0, __shfl_xor_sync(0xffffffffu, mt0, 1));
        mt0 = fmaxf(mt0, __shfl_xor_sync(0xffffffffu, mt0, 2));
        mt1 = fmaxf(mt1, __shfl_xor_sync(0xffffffffu, mt1, 1));
        mt1 = fmaxf(mt1, __shfl_xor_sync(0xffffffffu, mt1, 2));
        float mn0 = fmaxf(m0_, mt0);
        float mn1 = fmaxf(m1_, mt1);
        float cr0 = exp2f(m0_ - mn0);
        float cr1 = exp2f(m1_ - mn1);
        float rs0 = 0.f, rs1 = 0.f;
        #pragma unroll
        for (int nf = 0; nf < 8; nf++) {
            s[nf][0] = exp2f(s[nf][0] - mn0);
            s[nf][1] = exp2f(s[nf][1] - mn0);
            s[nf][2] = exp2f(s[nf][2] - mn1);
            s[nf][3] = exp2f(s[nf][3] - mn1);
            rs0 += s[nf][0] + s[nf][1];
            rs1 += s[nf][2] + s[nf][3];
        }
        rs0 += __shfl_xor_sync(0xffffffffu, rs0, 1);
        rs0 += __shfl_xor_sync(0xffffffffu, rs0, 2);
        rs1 += __shfl_xor_sync(0xffffffffu, rs1, 1);
        rs1 += __shfl_xor_sync(0xffffffffu, rs1, 2);
        l0_ = l0_ * cr0 + rs0;
        l1_ = l1_ * cr1 + rs1;
        m0_ = mn0; m1_ = mn1;
        #pragma unroll
        for (int nf = 0; nf < 8; nf++) {
            o[nf][0] *= cr0; o[nf][1] *= cr0;
            o[nf][2] *= cr1; o[nf][3] *= cr1;
        }

        // ---- P fragments ----
        uint32_t ph[4][4];
        #pragma unroll
        for (int kk = 0; kk < 4; kk++) {
            ph[kk][0] = pack2(s[2*kk][0],   s[2*kk][1]);
            ph[kk][1] = pack2(s[2*kk][2],   s[2*kk][3]);
            ph[kk][2] = pack2(s[2*kk+1][0], s[2*kk+1][1]);
            ph[kk][3] = pack2(s[2*kk+1][2], s[2*kk+1][3]);
        }

        // ---- O += P V ----
        #pragma unroll
        for (int kk = 0; kk < 4; kk++) {
            #pragma unroll
            for (int p = 0; p < 4; p++) {
                uint32_t offv = (uint32_t)((kk * 16 + lrow) * FSTR + p * 16 + lkad) * 2;
                uint32_t rv[4];
                ldsm4t(rv, sVh + offv);
                mma_f16(o[2*p],   ph[kk], rv[0], rv[1]);
                mma_f16(o[2*p+1], ph[kk], rv[2], rv[3]);
            }
        }
    }

    // ---- epilogue ----
    const float inv0 = 1.f / l0_;
    const float inv1 = 1.f / l1_;
    const int t0 = qt * 64 + w * 16 + (l >> 2);
    #pragma unroll
    for (int nf = 0; nf < 8; nf++) {
        int col = hh * 64 + nf * 8 + (l & 3) * 2;
        #pragma unroll
        for (int hf = 0; hf < 2; hf++) {
            int t = t0 + hf * 8;
            float inv = hf ? inv1 : inv0;
            size_t idx = ((size_t)(b * TT + t) << 10) + col;
            *(uint32_t*)&g_yh[idx] = pack2(o[nf][hf*2 + 0] * inv,
                                           o[nf][hf*2 + 1] * inv);
        }
    }
}

// ---------------------------------------------------------------------------
extern "C" void kernel_launch(void* const* d_in, const int* in_sizes, int n_in,
                              void* d_out, int out_size)
{
    const float* x  = (const float*)d_in[0];
    const float* Wq = (const float*)d_in[1];
    const float* Wk = (const float*)d_in[2];
    const float* Wv = (const float*)d_in[3];
    const float* Wp = (const float*)d_in[4];
    float* out = (float*)d_out;

    cudaFuncSetAttribute(gemm_qkv,  cudaFuncAttributeMaxDynamicSharedMemorySize, GSMEM);
    cudaFuncSetAttribute(gemm_proj, cudaFuncAttributeMaxDynamicSharedMemorySize, GSMEM);
    cudaFuncSetAttribute(flash_mma, cudaFuncAttributeMaxDynamicSharedMemorySize, FSMEM);

    size_t total_pairs = XPAIRS + 4 * WPAIRS;   // 6M
    cvt_inputs<<<(unsigned)((total_pairs + 255) / 256), 256>>>(x, Wq, Wk, Wv, Wp);

    gemm_qkv<<<dim3(CC/128, MM/128, 3), 128, GSMEM>>>();
    flash_mma<<<dim3(TT/64, BB*HH), 128, FSMEM>>>();
    gemm_proj<<<dim3(CC/128, MM/128), 128, GSMEM>>>(out);
}

// round 17
// speedup vs baseline: 1.0455x; 1.0455x over previous
#include <cuda_runtime.h>
#include <cuda_fp16.h>
#include <cstdint>

#define BB 4
#define TT 2048
#define CC 1024
#define HH 16
#define DD 64
#define MM (BB*TT)   // 8192

// logits pre-scale: 1/sqrt(D) * log2(e), folded into q at projection time
#define QSCALE 0.18033688011112042f

// ---------------------------------------------------------------------------
// Scratch (device globals, 16B aligned)
// ---------------------------------------------------------------------------
__device__ __align__(16) __half g_xh[(size_t)MM*CC];
__device__ __align__(16) __half g_wh[(size_t)4*CC*CC];   // q,k,v,p
__device__ __align__(16) __half g_qh[(size_t)MM*CC];     // [B,H,T,D] (pre-scaled)
__device__ __align__(16) __half g_kh[(size_t)MM*CC];
__device__ __align__(16) __half g_vh[(size_t)MM*CC];
__device__ __align__(16) __half g_yh[(size_t)MM*CC];     // [B,T,C]

// ---------------------------------------------------------------------------
// PTX helpers
// ---------------------------------------------------------------------------
__device__ __forceinline__ uint32_t smem_u32(const void* p) {
    uint32_t a;
    asm("{ .reg .u64 t; cvta.to.shared.u64 t, %1; cvt.u32.u64 %0, t; }"
        : "=r"(a) : "l"(p));
    return a;
}
__device__ __forceinline__ void cp16(uint32_t dst, const void* src) {
    asm volatile("cp.async.cg.shared.global [%0], [%1], 16;" :: "r"(dst), "l"(src));
}
__device__ __forceinline__ void cp_commit() {
    asm volatile("cp.async.commit_group;" ::: "memory");
}
template<int N> __device__ __forceinline__ void cp_wait() {
    asm volatile("cp.async.wait_group %0;" :: "n"(N) : "memory");
}
__device__ __forceinline__ void ldsm4(uint32_t* r, uint32_t a) {
    asm volatile("ldmatrix.sync.aligned.m8n8.x4.shared.b16 {%0,%1,%2,%3}, [%4];"
        : "=r"(r[0]), "=r"(r[1]), "=r"(r[2]), "=r"(r[3]) : "r"(a));
}
__device__ __forceinline__ void ldsm4t(uint32_t* r, uint32_t a) {
    asm volatile("ldmatrix.sync.aligned.m8n8.x4.trans.shared.b16 {%0,%1,%2,%3}, [%4];"
        : "=r"(r[0]), "=r"(r[1]), "=r"(r[2]), "=r"(r[3]) : "r"(a));
}
__device__ __forceinline__ void mma_f16(float* d, const uint32_t* a, uint32_t b0, uint32_t b1) {
    asm volatile(
        "mma.sync.aligned.m16n8k16.row.col.f32.f16.f16.f32 "
        "{%0,%1,%2,%3}, {%4,%5,%6,%7}, {%8,%9}, {%0,%1,%2,%3};"
        : "+f"(d[0]), "+f"(d[1]), "+f"(d[2]), "+f"(d[3])
        : "r"(a[0]), "r"(a[1]), "r"(a[2]), "r"(a[3]), "r"(b0), "r"(b1));
}
__device__ __forceinline__ uint32_t pack2(float a, float b) {
    __half2 h = __float22half2_rn(make_float2(a, b));   // single F2FP.PACK
    return *(uint32_t*)&h;
}

// ---------------------------------------------------------------------------
// Fused conversion: x -> fp16, W{q,k,v,p} -> fp16. 2 elems/thread.
// ---------------------------------------------------------------------------
#define XPAIRS ((size_t)MM*CC/2)     // 4194304
#define WPAIRS ((size_t)CC*CC/2)     // 524288

__global__ void cvt_inputs(const float* __restrict__ x,
                           const float* __restrict__ Wq, const float* __restrict__ Wk,
                           const float* __restrict__ Wv, const float* __restrict__ Wp) {
    size_t i = (size_t)blockIdx.x * blockDim.x + threadIdx.x;
    if (i < XPAIRS) {
        float2 v = ((const float2*)x)[i];
        ((__half2*)g_xh)[i] = __float22half2_rn(make_float2(v.x, v.y));
    } else {
        size_t j = i - XPAIRS;
        int which = (int)(j >> 19);
        size_t wi = j & (WPAIRS - 1);
        const float* src = (which == 0) ? Wq : (which == 1) ? Wk : (which == 2) ? Wv : Wp;
        float2 v = ((const float2*)src)[wi];
        ((__half2*)g_wh)[(size_t)which * WPAIRS + wi] =
            __float22half2_rn(make_float2(v.x, v.y));
    }
}

// ---------------------------------------------------------------------------
// GEMM: C[64x128] = Ah * Wh^T, fp16 1-term.
// 128 threads = 4 warps (1m x 4n), warp tile 64x32, target 5 CTAs/SM.
// smem: 2 stages x (Ah 64x32, Bh 128x32) fp16, row stride 40.
// ---------------------------------------------------------------------------
#define GSTR 40
#define GA_ELEMS (64*GSTR)           // 2560 elems per A tile
#define GB_ELEMS (128*GSTR)          // 5120 elems per B tile
#define GSTAGE_B ((GA_ELEMS + GB_ELEMS)*2)     // 15360 bytes per stage
#define GSMEM (2*GSTAGE_B)           // 30720

__device__ __forceinline__ void gemm_issue(
    uint32_t sb, int stage,
    const __half* __restrict__ Ah, const __half* __restrict__ Bh,
    int m0, int n0, int k0)
{
    const int t = threadIdx.x;
    const uint32_t stb = sb + stage * GSTAGE_B;
    #pragma unroll
    for (int i = 0; i < 2; i++) {
        int idx = i * 128 + t;
        int row = idx >> 2, c16 = idx & 3;
        cp16(stb + (uint32_t)(row * GSTR + c16 * 8) * 2,
             Ah + (size_t)(m0 + row) * CC + k0 + c16 * 8);
    }
    #pragma unroll
    for (int i = 0; i < 4; i++) {
        int idx = i * 128 + t;
        int row = idx >> 2, c16 = idx & 3;
        cp16(stb + (uint32_t)(GA_ELEMS + row * GSTR + c16 * 8) * 2,
             Bh + (size_t)(n0 + row) * CC + k0 + c16 * 8);
    }
}

__device__ __forceinline__ void gemm_body(
    const __half* __restrict__ Ah, const __half* __restrict__ Bh,
    int m0, int n0, uint32_t sb, float acc[4][4][4])
{
    const int l  = threadIdx.x & 31;
    const int wn = threadIdx.x >> 5;     // 0..3

    #pragma unroll
    for (int mf = 0; mf < 4; mf++)
        #pragma unroll
        for (int nf = 0; nf < 4; nf++)
            #pragma unroll
            for (int q = 0; q < 4; q++) acc[mf][nf][q] = 0.f;

    gemm_issue(sb, 0, Ah, Bh, m0, n0, 0);
    cp_commit();

    const uint32_t lrow = (l & 15);
    const uint32_t lkad = ((l >> 4) << 3);

    #pragma unroll 1
    for (int c = 0; c < 32; c++) {
        cp_wait<0>();            // chunk c landed
        __syncthreads();         // all 4 warps done with chunk c-1 -> stage free
        if (c + 1 < 32)
            gemm_issue(sb, (c + 1) & 1, Ah, Bh, m0, n0, (c + 1) * 32);
        cp_commit();             // uniform group count

        const uint32_t stb = sb + (c & 1) * GSTAGE_B;
        const uint32_t tAh = stb;
        const uint32_t tBh = stb + GA_ELEMS * 2;

        #pragma unroll
        for (int ks = 0; ks < 32; ks += 16) {
            uint32_t ah[4][4];
            #pragma unroll
            for (int mf = 0; mf < 4; mf++) {
                uint32_t off = (uint32_t)((mf * 16 + lrow) * GSTR + ks + lkad) * 2;
                ldsm4(ah[mf], tAh + off);
            }
            uint32_t bh[4][2];
            #pragma unroll
            for (int p = 0; p < 2; p++) {
                uint32_t off = (uint32_t)((wn * 32 + p * 16 + lrow) * GSTR + ks + lkad) * 2;
                uint32_t r[4];
                ldsm4(r, tBh + off);
                bh[2*p][0]   = r[0]; bh[2*p][1]   = r[2];
                bh[2*p+1][0] = r[1]; bh[2*p+1][1] = r[3];
            }
            #pragma unroll
            for (int mf = 0; mf < 4; mf++)
                #pragma unroll
                for (int nf = 0; nf < 4; nf++)
                    mma_f16(acc[mf][nf], ah[mf], bh[nf][0], bh[nf][1]);
        }
    }
}

// Fused QKV projection (1-term): grid (8, 128, 3). [B,H,T,D] fp16 out.
// q gets QSCALE folded in.
__global__ __launch_bounds__(128, 5)
void gemm_qkv() {
    extern __shared__ __align__(16) char gsm[];
    const uint32_t sb = smem_u32(gsm);
    const int which = blockIdx.z;            // 0=Q, 1=K, 2=V
    const int m0 = blockIdx.y * 64;
    const int n0 = blockIdx.x * 128;
    const __half* Wh = g_wh + (size_t)which * CC * CC;

    float acc[4][4][4];
    gemm_body(g_xh, Wh, m0, n0, sb, acc);

    __half* dst = (which == 0) ? g_qh : (which == 1) ? g_kh : g_vh;
    const float scl = (which == 0) ? QSCALE : 1.0f;
    const int l  = threadIdx.x & 31;
    const int wn = threadIdx.x >> 5;

    #pragma unroll
    for (int mf = 0; mf < 4; mf++) {
        #pragma unroll
        for (int nf = 0; nf < 4; nf++) {
            int col = n0 + wn * 32 + nf * 8 + (l & 3) * 2;
            int hh = col >> 6, d = col & 63;
            #pragma unroll
            for (int hf = 0; hf < 2; hf++) {
                int m = m0 + mf * 16 + (l >> 2) + hf * 8;
                int b = m >> 11, t = m & (TT - 1);
                size_t idx = (((size_t)(b * HH + hh) * TT + t) << 6) + d;
                *(uint32_t*)&dst[idx] = pack2(acc[mf][nf][hf*2 + 0] * scl,
                                              acc[mf][nf][hf*2 + 1] * scl);
            }
        }
    }
}

// Output projection (1-term): grid (8, 128); fp32 out
__global__ __launch_bounds__(128, 5)
void gemm_proj(float* __restrict__ out) {
    extern __shared__ __align__(16) char gsm[];
    const uint32_t sb = smem_u32(gsm);
    const int m0 = blockIdx.y * 64;
    const int n0 = blockIdx.x * 128;
    const __half* Wh = g_wh + (size_t)3 * CC * CC;

    float acc[4][4][4];
    gemm_body(g_yh, Wh, m0, n0, sb, acc);

    const int l  = threadIdx.x & 31;
    const int wn = threadIdx.x >> 5;

    #pragma unroll
    for (int mf = 0; mf < 4; mf++)
        #pragma unroll
        for (int nf = 0; nf < 4; nf++) {
            int col = n0 + wn * 32 + nf * 8 + (l & 3) * 2;
            #pragma unroll
            for (int hf = 0; hf < 2; hf++) {
                int m = m0 + mf * 16 + (l >> 2) + hf * 8;
                *(float2*)&out[(size_t)m * CC + col] =
                    make_float2(acc[mf][nf][hf*2 + 0], acc[mf][nf][hf*2 + 1]);
            }
        }
}

// ---------------------------------------------------------------------------
// Flash attention (round-12 exact). grid (32, 64), 128 thr (4 warps).
// BR=64 (16/warp), BC=64. exp2f softmax, QK 1-term, PV 1-term.
// KV 2-stage cp.async ring, 4 CTAs/SM.
// ---------------------------------------------------------------------------
#define FSTR 72
#define FKV_T (64*FSTR)              // 4608 elems per KV tile
#define FKV_STAGE_B (2*FKV_T*2)      // 18432 bytes per stage (Kh, Vh)
#define FQ_T (64*FSTR)               // 4608 elems Q tile
#define FQ_OFF (2*FKV_STAGE_B)       // 36864
#define FSMEM (FQ_OFF + FQ_T*2)      // 46080

__device__ __forceinline__ void kv_issue(uint32_t sb, int stage, size_t hb, int jt) {
    const int t = threadIdx.x;
    const uint32_t stb = sb + stage * FKV_STAGE_B;
    #pragma unroll
    for (int i = 0; i < 8; i++) {
        const int tile = i >> 2;                 // 0=K, 1=V
        int idx = ((i & 3) << 7) | t;            // 0..511
        int row = idx >> 3;
        int c16 = idx & 7;
        size_t go = hb + (size_t)(jt * 64 + row) * DD + c16 * 8;
        const __half* src = (tile == 0) ? (g_kh + go) : (g_vh + go);
        cp16(stb + (uint32_t)(tile * FKV_T + row * FSTR + c16 * 8) * 2, src);
    }
}

__global__ __launch_bounds__(128, 4)
void flash_mma() {
    extern __shared__ __align__(16) char fsm[];
    const uint32_t sb = smem_u32(fsm);

    const int tid = threadIdx.x;
    const int l   = tid & 31;
    const int w   = tid >> 5;            // 0..3
    const int qt  = (int)(gridDim.x - 1 - blockIdx.x);
    const int bh  = blockIdx.y;
    const int b   = bh >> 4;
    const int hh  = bh & 15;
    const size_t hb = (size_t)bh * TT * DD;
    const int ntile = qt + 1;

    // Q load + kv0 in one group
    #pragma unroll
    for (int i = 0; i < 4; i++) {
        int idx = (i << 7) | tid;                // 0..511
        int row = idx >> 3;
        int c16 = idx & 7;
        const __half* src = g_qh + hb + (size_t)(qt * 64 + row) * DD + c16 * 8;
        cp16(sb + FQ_OFF + (uint32_t)(row * FSTR + c16 * 8) * 2, src);
    }
    kv_issue(sb, 0, hb, 0);
    cp_commit();

    float s[8][4], o[8][4];
    float m0_ = -1e30f, m1_ = -1e30f, l0_ = 0.f, l1_ = 0.f;
    #pragma unroll
    for (int nf = 0; nf < 8; nf++)
        #pragma unroll
        for (int q = 0; q < 4; q++) o[nf][q] = 0.f;

    const uint32_t sQh = sb + FQ_OFF;
    const uint32_t lrow = (l & 15);
    const uint32_t lkad = ((l >> 4) << 3);

    #pragma unroll 1
    for (int jt = 0; jt < ntile; jt++) {
        cp_wait<0>();
        __syncthreads();
        if (jt + 1 < ntile)
            kv_issue(sb, (jt + 1) & 1, hb, jt + 1);
        cp_commit();

        const uint32_t kvb = sb + (jt & 1) * FKV_STAGE_B;
        const uint32_t sKh = kvb;
        const uint32_t sVh = kvb + FKV_T * 2;

        // ---- S = Q K^T (1-term) ----
        #pragma unroll
        for (int nf = 0; nf < 8; nf++)
            #pragma unroll
            for (int q = 0; q < 4; q++) s[nf][q] = 0.f;

        #pragma unroll
        for (int kd = 0; kd < 4; kd++) {
            uint32_t qh[4];
            uint32_t offq = (uint32_t)((w * 16 + lrow) * FSTR + kd * 16 + lkad) * 2;
            ldsm4(qh, sQh + offq);
            uint32_t rk[4][4];
            #pragma unroll
            for (int p = 0; p < 4; p++) {
                uint32_t offk = (uint32_t)((p * 16 + lrow) * FSTR + kd * 16 + lkad) * 2;
                ldsm4(rk[p], sKh + offk);
            }
            #pragma unroll
            for (int p = 0; p < 4; p++) {
                mma_f16(s[2*p],   qh, rk[p][0], rk[p][2]);
                mma_f16(s[2*p+1], qh, rk[p][1], rk[p][3]);
            }
        }

        // ---- causal mask (log2 domain) ----
        const int row_lo = qt * 64 + w * 16 + (l >> 2);
        const int row_hi = row_lo + 8;
        const int col0 = jt * 64 + (l & 3) * 2;
        if (jt == qt) {
            #pragma unroll
            for (int nf = 0; nf < 8; nf++) {
                int c = col0 + nf * 8;
                if (c     > row_lo) s[nf][0] = -1e30f;
                if (c + 1 > row_lo) s[nf][1] = -1e30f;
                if (c     > row_hi) s[nf][2] = -1e30f;
                if (c + 1 > row_hi) s[nf][3] = -1e30f;
            }
        }

        // ---- online softmax (base 2) ----
        float mt0 = -1e30f, mt1 = -1e30f;
        #pragma unroll
        for (int nf = 0; nf < 8; nf++) {
            mt0 = fmaxf(mt0, fmaxf(s[nf][0], s[nf][1]));
            mt1 = fmaxf(mt1, fmaxf(s[nf][2], s[nf][3]));
        }
        mt0 = fmaxf(mt0, __shfl_xor_sync(0xffffffffu, mt0, 1));
        mt0 = fmaxf(mt0, __shfl_xor_sync(0xffffffffu, mt0, 2));
        mt1 = fmaxf(mt1, __shfl_xor_sync(0xffffffffu, mt1, 1));
        mt1 = fmaxf(mt1, __shfl_xor_sync(0xffffffffu, mt1, 2));
        float mn0 = fmaxf(m0_, mt0);
        float mn1 = fmaxf(m1_, mt1);
        float cr0 = exp2f(m0_ - mn0);
        float cr1 = exp2f(m1_ - mn1);
        float rs0 = 0.f, rs1 = 0.f;
        #pragma unroll
        for (int nf = 0; nf < 8; nf++) {
            s[nf][0] = exp2f(s[nf][0] - mn0);
            s[nf][1] = exp2f(s[nf][1] - mn0);
            s[nf][2] = exp2f(s[nf][2] - mn1);
            s[nf][3] = exp2f(s[nf][3] - mn1);
            rs0 += s[nf][0] + s[nf][1];
            rs1 += s[nf][2] + s[nf][3];
        }
        rs0 += __shfl_xor_sync(0xffffffffu, rs0, 1);
        rs0 += __shfl_xor_sync(0xffffffffu, rs0, 2);
        rs1 += __shfl_xor_sync(0xffffffffu, rs1, 1);
        rs1 += __shfl_xor_sync(0xffffffffu, rs1, 2);
        l0_ = l0_ * cr0 + rs0;
        l1_ = l1_ * cr1 + rs1;
        m0_ = mn0; m1_ = mn1;
        #pragma unroll
        for (int nf = 0; nf < 8; nf++) {
            o[nf][0] *= cr0; o[nf][1] *= cr0;
            o[nf][2] *= cr1; o[nf][3] *= cr1;
        }

        // ---- P fragments ----
        uint32_t ph[4][4];
        #pragma unroll
        for (int kk = 0; kk < 4; kk++) {
            ph[kk][0] = pack2(s[2*kk][0],   s[2*kk][1]);
            ph[kk][1] = pack2(s[2*kk][2],   s[2*kk][3]);
            ph[kk][2] = pack2(s[2*kk+1][0], s[2*kk+1][1]);
            ph[kk][3] = pack2(s[2*kk+1][2], s[2*kk+1][3]);
        }

        // ---- O += P V (1-term) ----
        #pragma unroll
        for (int kk = 0; kk < 4; kk++) {
            #pragma unroll
            for (int p = 0; p < 4; p++) {
                uint32_t offv = (uint32_t)((kk * 16 + lrow) * FSTR + p * 16 + lkad) * 2;
                uint32_t rv[4];
                ldsm4t(rv, sVh + offv);
                mma_f16(o[2*p],   ph[kk], rv[0], rv[1]);
                mma_f16(o[2*p+1], ph[kk], rv[2], rv[3]);
            }
        }
    }

    // ---- epilogue: normalize, write y as fp16 [B,T,C] ----
    const float inv0 = 1.f / l0_;
    const float inv1 = 1.f / l1_;
    const int t0 = qt * 64 + w * 16 + (l >> 2);
    #pragma unroll
    for (int nf = 0; nf < 8; nf++) {
        int col = hh * 64 + nf * 8 + (l & 3) * 2;
        #pragma unroll
        for (int hf = 0; hf < 2; hf++) {
            int t = t0 + hf * 8;
            float inv = hf ? inv1 : inv0;
            size_t idx = ((size_t)(b * TT + t) << 10) + col;
            *(uint32_t*)&g_yh[idx] = pack2(o[nf][hf*2 + 0] * inv,
                                           o[nf][hf*2 + 1] * inv);
        }
    }
}

// ---------------------------------------------------------------------------
extern "C" void kernel_launch(void* const* d_in, const int* in_sizes, int n_in,
                              void* d_out, int out_size)
{
    const float* x  = (const float*)d_in[0];
    const float* Wq = (const float*)d_in[1];
    const float* Wk = (const float*)d_in[2];
    const float* Wv = (const float*)d_in[3];
    const float* Wp = (const float*)d_in[4];
    float* out = (float*)d_out;

    cudaFuncSetAttribute(gemm_qkv,  cudaFuncAttributeMaxDynamicSharedMemorySize, GSMEM);
    cudaFuncSetAttribute(gemm_proj, cudaFuncAttributeMaxDynamicSharedMemorySize, GSMEM);
    cudaFuncSetAttribute(flash_mma, cudaFuncAttributeMaxDynamicSharedMemorySize, FSMEM);

    size_t total_pairs = XPAIRS + 4 * WPAIRS;   // 6M
    cvt_inputs<<<(unsigned)((total_pairs + 255) / 256), 256>>>(x, Wq, Wk, Wv, Wp);

    gemm_qkv<<<dim3(CC/128, MM/64, 3), 128, GSMEM>>>();
    flash_mma<<<dim3(TT/64, BB*HH), 128, FSMEM>>>();
    gemm_proj<<<dim3(CC/128, MM/64), 128, GSMEM>>>(out);
}